// round 11
// baseline (speedup 1.0000x reference)
#include <cuda_runtime.h>
#include <cstdint>
#include <cstddef>

// Problem constants
#define B_  64
#define L_  512
#define H_  512
#define BLH ((size_t)B_ * L_ * H_)   // 16,777,216

// ---------------- scratch (device globals; no allocation) ----------------
__device__ float g_x[BLH];
__device__ float g_z[BLH];
__device__ float g_v[BLH];
__device__ float g_q[BLH];
__device__ float g_k[BLH];
__device__ float g_a[BLH];           // B x L x L (L == H)
__device__ float g_sm[(size_t)L_ * L_];

// ---------------- small kernels ----------------
__global__ void embed_kernel(const int* __restrict__ positives,
                             const float* __restrict__ item_emb,
                             const float* __restrict__ pos_emb) {
    int bl = blockIdx.x;             // 0 .. B*L-1
    int l = bl & (L_ - 1);
    int idx = positives[bl];
    const float4* src = (const float4*)(item_emb + (size_t)idx * H_);
    const float4* pe  = (const float4*)(pos_emb + (size_t)l * H_);
    float4* dst = (float4*)(g_x + (size_t)bl * H_);
    int t = threadIdx.x;             // 128 threads, H/4 = 128 float4
    float4 a = src[t];
    float4 p = pe[t];
    a.x += p.x; a.y += p.y; a.z += p.z; a.w += p.w;
    dst[t] = a;
}

__global__ void smask_kernel(const float* __restrict__ w,
                             const float* __restrict__ g) {
    int i = blockIdx.x * blockDim.x + threadIdx.x;
    float wi = w[i];
    float t = (logf(wi / (1.0f - wi)) + g[i]) * 5.0f;   // / TEMP(0.2)
    g_sm[i] = 1.0f / (1.0f + expf(-t));
}

// ---------------- epilogues ----------------
struct EpiNone {
    __device__ __forceinline__ void apply(float&, int, int, int) const {}
};
struct EpiSilu {
    __device__ __forceinline__ void apply(float& v, int, int, int) const {
        v = v / (1.0f + expf(-v));
    }
};
struct EpiScaleBias {
    const float* gamma; const float* beta;
    __device__ __forceinline__ void apply(float& v, int, int, int j) const {
        v = v * gamma[j] + beta[j];
    }
};
struct EpiAttn {
    const int* mask;                 // [B, L]
    __device__ __forceinline__ void apply(float& v, int b, int i, int j) const {
        bool keep = (i == j) || (mask[b * L_ + j] != 0 && j <= i);
        float x = keep ? g_sm[(size_t)i * L_ + j] * v : 0.0f;
        x = fmaxf(x, 0.0f);
        v = x * x * (1.0f / ((float)L_ * (float)H_));
    }
};

// ---------------- tiled GEMM ----------------
// C[M,N] = A[M,K] * op(B) with op(B)=B[N,K]^T if TRANSB else B[K,N].
// BM=BN=128, BK=16, 256 threads, 8x8 per-thread microtile,
// double-buffered SMEM with register-staged global prefetch.
#define BM 128
#define BN 128
#define BKK 16

template<bool TRANSB, class Epi>
__global__ __launch_bounds__(256, 2)
void gemm_kernel(const float* __restrict__ Ag, const float* __restrict__ Bg,
                 float* __restrict__ Cg, int M, int N, int K,
                 size_t sA, size_t sB, size_t sC, Epi epi)
{
    const int b = blockIdx.z;
    const float* A = Ag + (size_t)b * sA;
    const float* Bp = Bg + (size_t)b * sB;
    float* C = Cg + (size_t)b * sC;
    const int bm = blockIdx.y * BM;
    const int bn = blockIdx.x * BN;

    __shared__ float As[2][BKK][BM + 4];
    __shared__ float Bs[2][BKK][BN + 4];

    const int tid  = threadIdx.x;
    const int arow = tid >> 2;               // 0..63 (and +64 for second half)
    const int akc  = (tid & 3) << 2;         // 0,4,8,12
    const int brow = tid >> 5;               // 0..7 (and +8)
    const int bnc  = (tid & 31) << 2;        // 0..124
    const int ty = tid >> 4;                 // 0..15
    const int tx = tid & 15;                 // 0..15

    float4 pa0, pa1, pb0, pb1;

    auto loadA = [&](int k0) {
        pa0 = *(const float4*)(A + (size_t)(bm + arow) * K + k0 + akc);
        pa1 = *(const float4*)(A + (size_t)(bm + arow + 64) * K + k0 + akc);
    };
    auto loadB = [&](int k0) {
        if (TRANSB) {
            pb0 = *(const float4*)(Bp + (size_t)(bn + arow) * K + k0 + akc);
            pb1 = *(const float4*)(Bp + (size_t)(bn + arow + 64) * K + k0 + akc);
        } else {
            pb0 = *(const float4*)(Bp + (size_t)(k0 + brow) * N + bn + bnc);
            pb1 = *(const float4*)(Bp + (size_t)(k0 + brow + 8) * N + bn + bnc);
        }
    };
    auto storeTiles = [&](int buf) {
        As[buf][akc + 0][arow] = pa0.x;
        As[buf][akc + 1][arow] = pa0.y;
        As[buf][akc + 2][arow] = pa0.z;
        As[buf][akc + 3][arow] = pa0.w;
        As[buf][akc + 0][arow + 64] = pa1.x;
        As[buf][akc + 1][arow + 64] = pa1.y;
        As[buf][akc + 2][arow + 64] = pa1.z;
        As[buf][akc + 3][arow + 64] = pa1.w;
        if (TRANSB) {
            Bs[buf][akc + 0][arow] = pb0.x;
            Bs[buf][akc + 1][arow] = pb0.y;
            Bs[buf][akc + 2][arow] = pb0.z;
            Bs[buf][akc + 3][arow] = pb0.w;
            Bs[buf][akc + 0][arow + 64] = pb1.x;
            Bs[buf][akc + 1][arow + 64] = pb1.y;
            Bs[buf][akc + 2][arow + 64] = pb1.z;
            Bs[buf][akc + 3][arow + 64] = pb1.w;
        } else {
            *(float4*)&Bs[buf][brow][bnc]     = pb0;
            *(float4*)&Bs[buf][brow + 8][bnc] = pb1;
        }
    };

    float acc[8][8];
#pragma unroll
    for (int i = 0; i < 8; i++)
#pragma unroll
        for (int j = 0; j < 8; j++) acc[i][j] = 0.0f;

    const int nk = K / BKK;
    loadA(0); loadB(0);
    storeTiles(0);
    __syncthreads();

    int buf = 0;
    for (int kt = 0; kt < nk; kt++) {
        if (kt + 1 < nk) { loadA((kt + 1) * BKK); loadB((kt + 1) * BKK); }
#pragma unroll
        for (int k = 0; k < BKK; k++) {
            float4 a0 = *(const float4*)&As[buf][k][ty * 8];
            float4 a1 = *(const float4*)&As[buf][k][ty * 8 + 4];
            float4 b0 = *(const float4*)&Bs[buf][k][tx * 8];
            float4 b1 = *(const float4*)&Bs[buf][k][tx * 8 + 4];
            float ar[8] = {a0.x, a0.y, a0.z, a0.w, a1.x, a1.y, a1.z, a1.w};
            float br[8] = {b0.x, b0.y, b0.z, b0.w, b1.x, b1.y, b1.z, b1.w};
#pragma unroll
            for (int i = 0; i < 8; i++)
#pragma unroll
                for (int j = 0; j < 8; j++)
                    acc[i][j] = fmaf(ar[i], br[j], acc[i][j]);
        }
        if (kt + 1 < nk) {
            storeTiles(buf ^ 1);
            __syncthreads();
            buf ^= 1;
        }
    }

    // epilogue + store
    const int gj0 = bn + tx * 8;
#pragma unroll
    for (int ii = 0; ii < 8; ii++) {
        int gi = bm + ty * 8 + ii;
        float vals[8];
#pragma unroll
        for (int jj = 0; jj < 8; jj++) {
            vals[jj] = acc[ii][jj];
            epi.apply(vals[jj], b, gi, gj0 + jj);
        }
        float* crow = C + (size_t)gi * N + gj0;
        *(float4*)crow       = make_float4(vals[0], vals[1], vals[2], vals[3]);
        *(float4*)(crow + 4) = make_float4(vals[4], vals[5], vals[6], vals[7]);
    }
}

// ---------------- launch ----------------
extern "C" void kernel_launch(void* const* d_in, const int* in_sizes, int n_in,
                              void* d_out, int out_size) {
    const int*   positives = (const int*)  d_in[0];
    const int*   mask      = (const int*)  d_in[1];
    const float* item_emb  = (const float*)d_in[2];
    const float* pos_emb   = (const float*)d_in[3];
    const float* Wz        = (const float*)d_in[4];
    const float* Wv        = (const float*)d_in[5];
    const float* Wq        = (const float*)d_in[6];
    const float* Wk        = (const float*)d_in[7];
    const float* gamma_q   = (const float*)d_in[8];
    const float* beta_q    = (const float*)d_in[9];
    const float* gamma_k   = (const float*)d_in[10];
    const float* beta_k    = (const float*)d_in[11];
    const float* sparse_w  = (const float*)d_in[12];
    const float* gumbel    = (const float*)d_in[13];
    float* out = (float*)d_out;

    float *x, *z, *v, *q, *k, *a;
    cudaGetSymbolAddress((void**)&x, g_x);
    cudaGetSymbolAddress((void**)&z, g_z);
    cudaGetSymbolAddress((void**)&v, g_v);
    cudaGetSymbolAddress((void**)&q, g_q);
    cudaGetSymbolAddress((void**)&k, g_k);
    cudaGetSymbolAddress((void**)&a, g_a);

    // 1. embeddings + sparse gate (independent)
    embed_kernel<<<B_ * L_, 128>>>(positives, item_emb, pos_emb);
    smask_kernel<<<(L_ * L_) / 256, 256>>>(sparse_w, gumbel);

    // 2. projections: [32768, 512] x [512, 512]^T
    dim3 gp(H_ / BN, (B_ * L_) / BM, 1);
    gemm_kernel<true, EpiSilu><<<gp, 256>>>(x, Wz, z, B_ * L_, H_, H_, 0, 0, 0, EpiSilu{});
    gemm_kernel<true, EpiSilu><<<gp, 256>>>(x, Wv, v, B_ * L_, H_, H_, 0, 0, 0, EpiSilu{});
    gemm_kernel<true, EpiScaleBias><<<gp, 256>>>(z, Wq, q, B_ * L_, H_, H_, 0, 0, 0,
                                                 EpiScaleBias{gamma_q, beta_q});
    gemm_kernel<true, EpiScaleBias><<<gp, 256>>>(z, Wk, k, B_ * L_, H_, H_, 0, 0, 0,
                                                 EpiScaleBias{gamma_k, beta_k});

    // 3. attention scores: a[b] = epi(q[b] @ k[b]^T)
    dim3 gb(L_ / BN, L_ / BM, B_);
    size_t sBLH = (size_t)L_ * H_;
    gemm_kernel<true, EpiAttn><<<gb, 256>>>(q, k, a, L_, L_, H_, sBLH, sBLH, sBLH,
                                            EpiAttn{mask});

    // 4. out[b] = a[b] @ v[b]
    gemm_kernel<false, EpiNone><<<gb, 256>>>(a, v, out, L_, H_, L_, sBLH, sBLH, sBLH,
                                             EpiNone{});
}

// round 12
// speedup vs baseline: 1.0006x; 1.0006x over previous
#include <cuda_runtime.h>
#include <cstdint>
#include <cstddef>

// Problem constants
#define B_  64
#define L_  512
#define H_  512
#define BLH ((size_t)B_ * L_ * H_)   // 16,777,216

// ---------------- scratch (device globals; no allocation) ----------------
__device__ float g_x[BLH];
__device__ float g_z[BLH];
__device__ float g_v[BLH];
__device__ float g_q[BLH];
__device__ float g_k[BLH];
__device__ float g_a[BLH];           // B x L x L (L == H)
__device__ float g_sm[(size_t)L_ * L_];

// ---------------- small kernels ----------------
__global__ void embed_kernel(const int* __restrict__ positives,
                             const float* __restrict__ item_emb,
                             const float* __restrict__ pos_emb) {
    int bl = blockIdx.x;             // 0 .. B*L-1
    int l = bl & (L_ - 1);
    int idx = positives[bl];
    const float4* src = (const float4*)(item_emb + (size_t)idx * H_);
    const float4* pe  = (const float4*)(pos_emb + (size_t)l * H_);
    float4* dst = (float4*)(g_x + (size_t)bl * H_);
    int t = threadIdx.x;             // 128 threads, H/4 = 128 float4
    float4 a = src[t];
    float4 p = pe[t];
    a.x += p.x; a.y += p.y; a.z += p.z; a.w += p.w;
    dst[t] = a;
}

__global__ void smask_kernel(const float* __restrict__ w,
                             const float* __restrict__ g) {
    int i = blockIdx.x * blockDim.x + threadIdx.x;
    float wi = w[i];
    float t = (logf(wi / (1.0f - wi)) + g[i]) * 5.0f;   // / TEMP(0.2)
    g_sm[i] = 1.0f / (1.0f + expf(-t));
}

// ---------------- epilogues ----------------
struct EpiNone {
    __device__ __forceinline__ void apply(float&, int, int, int) const {}
};
struct EpiSilu {
    __device__ __forceinline__ void apply(float& v, int, int, int) const {
        v = v / (1.0f + expf(-v));
    }
};
struct EpiScaleBias {
    const float* gamma; const float* beta;
    __device__ __forceinline__ void apply(float& v, int, int, int j) const {
        v = v * gamma[j] + beta[j];
    }
};
struct EpiAttn {
    const int* mask;                 // [B, L]
    __device__ __forceinline__ void apply(float& v, int b, int i, int j) const {
        bool keep = (i == j) || (mask[b * L_ + j] != 0 && j <= i);
        float x = keep ? g_sm[(size_t)i * L_ + j] * v : 0.0f;
        x = fmaxf(x, 0.0f);
        v = x * x * (1.0f / ((float)L_ * (float)H_));
    }
};

// ---------------- tiled GEMM ----------------
// C[M,N] = A[M,K] * op(B) with op(B)=B[N,K]^T if TRANSB else B[K,N].
// BM=BN=128, BK=16, 256 threads, 8x8 per-thread microtile,
// double-buffered SMEM with register-staged global prefetch.
#define BM 128
#define BN 128
#define BKK 16

template<bool TRANSB, class Epi>
__global__ __launch_bounds__(256, 2)
void gemm_kernel(const float* __restrict__ Ag, const float* __restrict__ Bg,
                 float* __restrict__ Cg, int M, int N, int K,
                 size_t sA, size_t sB, size_t sC, Epi epi)
{
    const int b = blockIdx.z;
    const float* A = Ag + (size_t)b * sA;
    const float* Bp = Bg + (size_t)b * sB;
    float* C = Cg + (size_t)b * sC;
    const int bm = blockIdx.y * BM;
    const int bn = blockIdx.x * BN;

    __shared__ float As[2][BKK][BM + 4];
    __shared__ float Bs[2][BKK][BN + 4];

    const int tid  = threadIdx.x;
    const int arow = tid >> 2;               // 0..63 (and +64 for second half)
    const int akc  = (tid & 3) << 2;         // 0,4,8,12
    const int brow = tid >> 5;               // 0..7 (and +8)
    const int bnc  = (tid & 31) << 2;        // 0..124
    const int ty = tid >> 4;                 // 0..15
    const int tx = tid & 15;                 // 0..15

    float4 pa0, pa1, pb0, pb1;

    auto loadA = [&](int k0) {
        pa0 = *(const float4*)(A + (size_t)(bm + arow) * K + k0 + akc);
        pa1 = *(const float4*)(A + (size_t)(bm + arow + 64) * K + k0 + akc);
    };
    auto loadB = [&](int k0) {
        if (TRANSB) {
            pb0 = *(const float4*)(Bp + (size_t)(bn + arow) * K + k0 + akc);
            pb1 = *(const float4*)(Bp + (size_t)(bn + arow + 64) * K + k0 + akc);
        } else {
            pb0 = *(const float4*)(Bp + (size_t)(k0 + brow) * N + bn + bnc);
            pb1 = *(const float4*)(Bp + (size_t)(k0 + brow + 8) * N + bn + bnc);
        }
    };
    auto storeTiles = [&](int buf) {
        As[buf][akc + 0][arow] = pa0.x;
        As[buf][akc + 1][arow] = pa0.y;
        As[buf][akc + 2][arow] = pa0.z;
        As[buf][akc + 3][arow] = pa0.w;
        As[buf][akc + 0][arow + 64] = pa1.x;
        As[buf][akc + 1][arow + 64] = pa1.y;
        As[buf][akc + 2][arow + 64] = pa1.z;
        As[buf][akc + 3][arow + 64] = pa1.w;
        if (TRANSB) {
            Bs[buf][akc + 0][arow] = pb0.x;
            Bs[buf][akc + 1][arow] = pb0.y;
            Bs[buf][akc + 2][arow] = pb0.z;
            Bs[buf][akc + 3][arow] = pb0.w;
            Bs[buf][akc + 0][arow + 64] = pb1.x;
            Bs[buf][akc + 1][arow + 64] = pb1.y;
            Bs[buf][akc + 2][arow + 64] = pb1.z;
            Bs[buf][akc + 3][arow + 64] = pb1.w;
        } else {
            *(float4*)&Bs[buf][brow][bnc]     = pb0;
            *(float4*)&Bs[buf][brow + 8][bnc] = pb1;
        }
    };

    float acc[8][8];
#pragma unroll
    for (int i = 0; i < 8; i++)
#pragma unroll
        for (int j = 0; j < 8; j++) acc[i][j] = 0.0f;

    const int nk = K / BKK;
    loadA(0); loadB(0);
    storeTiles(0);
    __syncthreads();

    int buf = 0;
    for (int kt = 0; kt < nk; kt++) {
        if (kt + 1 < nk) { loadA((kt + 1) * BKK); loadB((kt + 1) * BKK); }
#pragma unroll
        for (int k = 0; k < BKK; k++) {
            float4 a0 = *(const float4*)&As[buf][k][ty * 8];
            float4 a1 = *(const float4*)&As[buf][k][ty * 8 + 4];
            float4 b0 = *(const float4*)&Bs[buf][k][tx * 8];
            float4 b1 = *(const float4*)&Bs[buf][k][tx * 8 + 4];
            float ar[8] = {a0.x, a0.y, a0.z, a0.w, a1.x, a1.y, a1.z, a1.w};
            float br[8] = {b0.x, b0.y, b0.z, b0.w, b1.x, b1.y, b1.z, b1.w};
#pragma unroll
            for (int i = 0; i < 8; i++)
#pragma unroll
                for (int j = 0; j < 8; j++)
                    acc[i][j] = fmaf(ar[i], br[j], acc[i][j]);
        }
        if (kt + 1 < nk) {
            storeTiles(buf ^ 1);
            __syncthreads();
            buf ^= 1;
        }
    }

    // epilogue + store
    const int gj0 = bn + tx * 8;
#pragma unroll
    for (int ii = 0; ii < 8; ii++) {
        int gi = bm + ty * 8 + ii;
        float vals[8];
#pragma unroll
        for (int jj = 0; jj < 8; jj++) {
            vals[jj] = acc[ii][jj];
            epi.apply(vals[jj], b, gi, gj0 + jj);
        }
        float* crow = C + (size_t)gi * N + gj0;
        *(float4*)crow       = make_float4(vals[0], vals[1], vals[2], vals[3]);
        *(float4*)(crow + 4) = make_float4(vals[4], vals[5], vals[6], vals[7]);
    }
}

// ---------------- launch ----------------
extern "C" void kernel_launch(void* const* d_in, const int* in_sizes, int n_in,
                              void* d_out, int out_size) {
    const int*   positives = (const int*)  d_in[0];
    const int*   mask      = (const int*)  d_in[1];
    const float* item_emb  = (const float*)d_in[2];
    const float* pos_emb   = (const float*)d_in[3];
    const float* Wz        = (const float*)d_in[4];
    const float* Wv        = (const float*)d_in[5];
    const float* Wq        = (const float*)d_in[6];
    const float* Wk        = (const float*)d_in[7];
    const float* gamma_q   = (const float*)d_in[8];
    const float* beta_q    = (const float*)d_in[9];
    const float* gamma_k   = (const float*)d_in[10];
    const float* beta_k    = (const float*)d_in[11];
    const float* sparse_w  = (const float*)d_in[12];
    const float* gumbel    = (const float*)d_in[13];
    float* out = (float*)d_out;

    float *x, *z, *v, *q, *k, *a;
    cudaGetSymbolAddress((void**)&x, g_x);
    cudaGetSymbolAddress((void**)&z, g_z);
    cudaGetSymbolAddress((void**)&v, g_v);
    cudaGetSymbolAddress((void**)&q, g_q);
    cudaGetSymbolAddress((void**)&k, g_k);
    cudaGetSymbolAddress((void**)&a, g_a);

    // 1. embeddings + sparse gate (independent)
    embed_kernel<<<B_ * L_, 128>>>(positives, item_emb, pos_emb);
    smask_kernel<<<(L_ * L_) / 256, 256>>>(sparse_w, gumbel);

    // 2. projections: [32768, 512] x [512, 512]^T
    dim3 gp(H_ / BN, (B_ * L_) / BM, 1);
    gemm_kernel<true, EpiSilu><<<gp, 256>>>(x, Wz, z, B_ * L_, H_, H_, 0, 0, 0, EpiSilu{});
    gemm_kernel<true, EpiSilu><<<gp, 256>>>(x, Wv, v, B_ * L_, H_, H_, 0, 0, 0, EpiSilu{});
    gemm_kernel<true, EpiScaleBias><<<gp, 256>>>(z, Wq, q, B_ * L_, H_, H_, 0, 0, 0,
                                                 EpiScaleBias{gamma_q, beta_q});
    gemm_kernel<true, EpiScaleBias><<<gp, 256>>>(z, Wk, k, B_ * L_, H_, H_, 0, 0, 0,
                                                 EpiScaleBias{gamma_k, beta_k});

    // 3. attention scores: a[b] = epi(q[b] @ k[b]^T)
    dim3 gb(L_ / BN, L_ / BM, B_);
    size_t sBLH = (size_t)L_ * H_;
    gemm_kernel<true, EpiAttn><<<gb, 256>>>(q, k, a, L_, L_, H_, sBLH, sBLH, sBLH,
                                            EpiAttn{mask});

    // 4. out[b] = a[b] @ v[b]
    gemm_kernel<false, EpiNone><<<gb, 256>>>(a, v, out, L_, H_, L_, sBLH, sBLH, sBLH,
                                             EpiNone{});
}